// round 10
// baseline (speedup 1.0000x reference)
#include <cuda_runtime.h>
#include <cuda_fp16.h>
#include <math.h>
#include <stdint.h>

#define NDIM 4096

// ===================== scratch (no allocation allowed) =====================
__device__ __half g_xhi[(size_t)NDIM * NDIM];
__device__ __half g_xlo[(size_t)NDIM * NDIM];
__device__ __half g_wqhi[(size_t)NDIM * NDIM];
__device__ __half g_wqlo[(size_t)NDIM * NDIM];
__device__ __half g_wkhi[(size_t)NDIM * NDIM];
__device__ __half g_wklo[(size_t)NDIM * NDIM];
__device__ __half g_wvhi[(size_t)NDIM * NDIM];
__device__ __half g_wvlo[(size_t)NDIM * NDIM];
__device__ __half g_qhi[(size_t)NDIM * NDIM];
__device__ __half g_qlo[(size_t)NDIM * NDIM];
__device__ __half g_khi[(size_t)NDIM * NDIM];
__device__ __half g_klo[(size_t)NDIM * NDIM];
__device__ float  g_v  [(size_t)NDIM * NDIM];

// ===================== small PTX helpers =====================
__device__ __forceinline__ uint32_t smem_u32(const void* p) {
    uint32_t a;
    asm("{ .reg .u64 t; cvta.to.shared.u64 t, %1; cvt.u32.u64 %0, t; }" : "=r"(a) : "l"(p));
    return a;
}
__device__ __forceinline__ void cp16(uint32_t s, const void* g) {
    asm volatile("cp.async.cg.shared.global [%0], [%1], 16;" :: "r"(s), "l"(g));
}
#define CP_COMMIT() asm volatile("cp.async.commit_group;" ::: "memory")
#define CP_WAIT(n)  asm volatile("cp.async.wait_group %0;" :: "n"(n) : "memory")

__device__ __forceinline__ void ldsm4(uint32_t* r, uint32_t addr) {
    asm volatile("ldmatrix.sync.aligned.m8n8.x4.shared.b16 {%0,%1,%2,%3}, [%4];"
        : "=r"(r[0]), "=r"(r[1]), "=r"(r[2]), "=r"(r[3]) : "r"(addr));
}
// fp16 inputs, fp32 accumulate (main term)
__device__ __forceinline__ void mma_f32(float* c, const uint32_t* a, uint32_t b0, uint32_t b1) {
    asm volatile("mma.sync.aligned.m16n8k16.row.col.f32.f16.f16.f32 "
        "{%0,%1,%2,%3},{%4,%5,%6,%7},{%8,%9},{%0,%1,%2,%3};"
        : "+f"(c[0]), "+f"(c[1]), "+f"(c[2]), "+f"(c[3])
        : "r"(a[0]), "r"(a[1]), "r"(a[2]), "r"(a[3]), "r"(b0), "r"(b1));
}
// fp16 inputs, fp16 accumulate (correction terms)
__device__ __forceinline__ void mma_f16(uint32_t* c, const uint32_t* a, uint32_t b0, uint32_t b1) {
    asm volatile("mma.sync.aligned.m16n8k16.row.col.f16.f16.f16.f16 "
        "{%0,%1},{%2,%3,%4,%5},{%6,%7},{%0,%1};"
        : "+r"(c[0]), "+r"(c[1])
        : "r"(a[0]), "r"(a[1]), "r"(a[2]), "r"(a[3]), "r"(b0), "r"(b1));
}

// Tile rows are 64B (4 x 16B chunks); chunk permuted by (row>>1)&3.
__device__ __forceinline__ uint32_t sw_addr(uint32_t tile_base, int row, int c) {
    return tile_base + row * 64 + ((c ^ ((row >> 1) & 3)) << 4);
}

// ===================== merged fp32 -> fp16 hi/lo split (z selects tensor) ==
__global__ void __launch_bounds__(256)
split_hi_lo4(const float* __restrict__ i0, __half* __restrict__ h0p, __half* __restrict__ l0p,
             const float* __restrict__ i1, __half* __restrict__ h1p, __half* __restrict__ l1p,
             const float* __restrict__ i2, __half* __restrict__ h2p, __half* __restrict__ l2p,
             const float* __restrict__ i3, __half* __restrict__ h3p, __half* __restrict__ l3p)
{
    const float* in;
    __half *hi, *lo;
    switch (blockIdx.z) {
        case 0: in = i0; hi = h0p; lo = l0p; break;
        case 1: in = i1; hi = h1p; lo = l1p; break;
        case 2: in = i2; hi = h2p; lo = l2p; break;
        default: in = i3; hi = h3p; lo = l3p; break;
    }
    size_t i = ((size_t)blockIdx.x * 256 + threadIdx.x) * 4;
    float4 v = *(const float4*)(in + i);
    __half a0 = __float2half_rn(v.x), a1 = __float2half_rn(v.y);
    __half a2 = __float2half_rn(v.z), a3 = __float2half_rn(v.w);
    __half b0 = __float2half_rn(v.x - __half2float(a0));
    __half b1 = __float2half_rn(v.y - __half2float(a1));
    __half b2 = __float2half_rn(v.z - __half2float(a2));
    __half b3 = __float2half_rn(v.w - __half2float(a3));
    *(__half2*)(hi + i)     = __halves2half2(a0, a1);
    *(__half2*)(hi + i + 2) = __halves2half2(a2, a3);
    *(__half2*)(lo + i)     = __halves2half2(b0, b1);
    *(__half2*)(lo + i + 2) = __halves2half2(b2, b3);
}

// ===================== HMMA GEMM =====================
// C = A*B^T with A ~ Ahi+Alo, B ~ Bhi+Blo (fp16 2-term split).
// Main product hh in fp32 acc; corrections (lh + hl) share one fp16 acc.
// CTA tile 128x128, BK=32, 4-stage cp.async pipeline, 8 warps @ 64x32, 1 CTA/SM.
// MODE 0: Cf = alpha*(acc + bias[n])                  (v projection)
// MODE 1: split(alpha*(acc + bias[n])) -> Chi, Clo    (q/k projections)
// MODE 2: Cf = alpha*acc                              (attention logits)
#define NSTAGE 4
#define STAGE_B 32768
#define OFF_AHI 0
#define OFF_ALO 8192
#define OFF_BHI 16384
#define OFF_BLO 24576
#define DYN_SMEM (NSTAGE * STAGE_B)

__device__ __forceinline__ void load_stage(
    uint32_t sb, int stage, int k0, int m0, int n0, int tid,
    const __half* __restrict__ Ahi, const __half* __restrict__ Alo,
    const __half* __restrict__ Bhi, const __half* __restrict__ Blo)
{
    const uint32_t st = sb + stage * STAGE_B;
#pragma unroll
    for (int i = 0; i < 2; i++) {
        const int slot = tid + i * 256;        // 0..511
        const int r = slot >> 2;               // 0..127
        const int c = slot & 3;                // 16B chunk in 64B row
        const uint32_t sw = sw_addr(0, r, c);
        const size_t ga = (size_t)(m0 + r) * NDIM + k0 + c * 8;
        const size_t gb = (size_t)(n0 + r) * NDIM + k0 + c * 8;
        cp16(st + OFF_AHI + sw, Ahi + ga);
        cp16(st + OFF_ALO + sw, Alo + ga);
        cp16(st + OFF_BHI + sw, Bhi + gb);
        cp16(st + OFF_BLO + sw, Blo + gb);
    }
}

template<int MODE>
__global__ void __launch_bounds__(256, 1)
gemm_f16x2(const __half* __restrict__ Ahi, const __half* __restrict__ Alo,
           const __half* __restrict__ Bhi, const __half* __restrict__ Blo,
           const float* __restrict__ bias, float alpha,
           float* __restrict__ Cf,
           __half* __restrict__ Chi, __half* __restrict__ Clo)
{
    extern __shared__ char dynsmem[];
    const uint32_t sb = smem_u32(dynsmem);
    const int tid  = threadIdx.x;
    const int lane = tid & 31;
    const int w    = tid >> 5;           // 0..7
    const int wm0  = (w & 1) * 64;       // 2 warps along m
    const int wn0  = (w >> 1) * 32;      // 4 warps along n
    const int m0 = blockIdx.y * 128;
    const int n0 = blockIdx.x * 128;

    float acc[4][4][4];
    uint32_t acc16[4][4][2];
#pragma unroll
    for (int mt = 0; mt < 4; mt++)
#pragma unroll
        for (int nt = 0; nt < 4; nt++) {
#pragma unroll
            for (int e = 0; e < 4; e++) acc[mt][nt][e] = 0.0f;
            acc16[mt][nt][0] = 0u; acc16[mt][nt][1] = 0u;
        }

#pragma unroll
    for (int s = 0; s < NSTAGE - 1; s++) {
        load_stage(sb, s, s * 32, m0, n0, tid, Ahi, Alo, Bhi, Blo);
        CP_COMMIT();
    }

    const int arow  = (lane & 15);
    const int ahalf = (lane >> 4);

    for (int i = 0; i < NDIM / 32; i++) {
        CP_WAIT(NSTAGE - 2);
        __syncthreads();
        const int j = i + NSTAGE - 1;
        if (j < NDIM / 32)
            load_stage(sb, j % NSTAGE, j * 32, m0, n0, tid, Ahi, Alo, Bhi, Blo);
        CP_COMMIT();

        const uint32_t st = sb + (i % NSTAGE) * STAGE_B;
#pragma unroll
        for (int ks = 0; ks < 2; ks++) {
            const int c = ks * 2 + ahalf;
            uint32_t bh[2][4], bl[2][4];
#pragma unroll
            for (int p = 0; p < 2; p++) {
                const int r = wn0 + p * 16 + arow;
                ldsm4(bh[p], sw_addr(st + OFF_BHI, r, c));
                ldsm4(bl[p], sw_addr(st + OFF_BLO, r, c));
            }
#pragma unroll
            for (int mt = 0; mt < 4; mt++) {
                const int r = wm0 + mt * 16 + arow;
                uint32_t ah[4], al[4];
                ldsm4(ah, sw_addr(st + OFF_AHI, r, c));
                ldsm4(al, sw_addr(st + OFF_ALO, r, c));
                // main term: hh, fp32 accumulate (4 independent accs)
                mma_f32(acc[mt][0], ah, bh[0][0], bh[0][2]);
                mma_f32(acc[mt][1], ah, bh[0][1], bh[0][3]);
                mma_f32(acc[mt][2], ah, bh[1][0], bh[1][2]);
                mma_f32(acc[mt][3], ah, bh[1][1], bh[1][3]);
                // corrections: lh then hl, fp16 accumulate (shared acc)
                mma_f16(acc16[mt][0], al, bh[0][0], bh[0][2]);
                mma_f16(acc16[mt][1], al, bh[0][1], bh[0][3]);
                mma_f16(acc16[mt][2], al, bh[1][0], bh[1][2]);
                mma_f16(acc16[mt][3], al, bh[1][1], bh[1][3]);
                mma_f16(acc16[mt][0], ah, bl[0][0], bl[0][2]);
                mma_f16(acc16[mt][1], ah, bl[0][1], bl[0][3]);
                mma_f16(acc16[mt][2], ah, bl[1][0], bl[1][2]);
                mma_f16(acc16[mt][3], ah, bl[1][1], bl[1][3]);
            }
        }
    }

    // ---------------- epilogue ----------------
#pragma unroll
    for (int mt = 0; mt < 4; mt++) {
#pragma unroll
        for (int nt = 0; nt < 4; nt++) {
            const int r0  = m0 + wm0 + mt * 16 + (lane >> 2);
            const int col = n0 + wn0 + nt * 8 + (lane & 3) * 2;
            const float* cc = acc[mt][nt];
#pragma unroll
            for (int h = 0; h < 2; h++) {       // rows r0, r0+8
                const int r = r0 + h * 8;
                __half2 cr = *(__half2*)&acc16[mt][nt][h];
                float f0 = cc[2 * h + 0] + __half2float(__low2half(cr));
                float f1 = cc[2 * h + 1] + __half2float(__high2half(cr));
                if (MODE == 2) {
                    *(float2*)&Cf[(size_t)r * NDIM + col] = make_float2(f0 * alpha, f1 * alpha);
                } else if (MODE == 0) {
                    f0 = alpha * (f0 + __ldg(&bias[col]));
                    f1 = alpha * (f1 + __ldg(&bias[col + 1]));
                    *(float2*)&Cf[(size_t)r * NDIM + col] = make_float2(f0, f1);
                } else {
                    f0 = alpha * (f0 + __ldg(&bias[col]));
                    f1 = alpha * (f1 + __ldg(&bias[col + 1]));
                    __half h0 = __float2half_rn(f0), h1 = __float2half_rn(f1);
                    __half l0 = __float2half_rn(f0 - __half2float(h0));
                    __half l1 = __float2half_rn(f1 - __half2float(h1));
                    *(__half2*)&Chi[(size_t)r * NDIM + col] = __halves2half2(h0, h1);
                    *(__half2*)&Clo[(size_t)r * NDIM + col] = __halves2half2(l0, l1);
                }
            }
        }
    }
}

// ===================== softmax(S) * v, in place on d_out =====================
__global__ void __launch_bounds__(256)
softmax_mul(const float* __restrict__ S, const float* __restrict__ V, float* __restrict__ out)
{
    __shared__ float red[256];
    const int row = blockIdx.x;
    const int tid = threadIdx.x;
    const float* s = S + (size_t)row * NDIM;

    float vals[16];
    float m = -INFINITY;
#pragma unroll
    for (int i = 0; i < 16; i++) {
        vals[i] = s[tid + i * 256];
        m = fmaxf(m, vals[i]);
    }
    red[tid] = m;
    __syncthreads();
#pragma unroll
    for (int w = 128; w > 0; w >>= 1) {
        if (tid < w) red[tid] = fmaxf(red[tid], red[tid + w]);
        __syncthreads();
    }
    m = red[0];
    __syncthreads();

    float sum = 0.0f;
#pragma unroll
    for (int i = 0; i < 16; i++) {
        vals[i] = expf(vals[i] - m);
        sum += vals[i];
    }
    red[tid] = sum;
    __syncthreads();
#pragma unroll
    for (int w = 128; w > 0; w >>= 1) {
        if (tid < w) red[tid] += red[tid + w];
        __syncthreads();
    }
    const float inv = 1.0f / red[0];

    const float* v = V + (size_t)row * NDIM;
    float* o = out + (size_t)row * NDIM;
#pragma unroll
    for (int i = 0; i < 16; i++) {
        const int c = tid + i * 256;
        o[c] = vals[i] * inv * v[c];
    }
}

// ===================== launch =====================
extern "C" void kernel_launch(void* const* d_in, const int* in_sizes, int n_in,
                              void* d_out, int out_size)
{
    const float* x  = (const float*)d_in[0];
    const float* Wq = (const float*)d_in[1];
    const float* bq = (const float*)d_in[2];
    const float* Wk = (const float*)d_in[3];
    const float* bk = (const float*)d_in[4];
    const float* Wv = (const float*)d_in[5];
    const float* bv = (const float*)d_in[6];
    float* out = (float*)d_out;

    __half *xhi, *xlo, *wqhi, *wqlo, *wkhi, *wklo, *wvhi, *wvlo;
    __half *qhi, *qlo, *khi, *klo;
    float* vp;
    cudaGetSymbolAddress((void**)&xhi,  g_xhi);
    cudaGetSymbolAddress((void**)&xlo,  g_xlo);
    cudaGetSymbolAddress((void**)&wqhi, g_wqhi);
    cudaGetSymbolAddress((void**)&wqlo, g_wqlo);
    cudaGetSymbolAddress((void**)&wkhi, g_wkhi);
    cudaGetSymbolAddress((void**)&wklo, g_wklo);
    cudaGetSymbolAddress((void**)&wvhi, g_wvhi);
    cudaGetSymbolAddress((void**)&wvlo, g_wvlo);
    cudaGetSymbolAddress((void**)&qhi,  g_qhi);
    cudaGetSymbolAddress((void**)&qlo,  g_qlo);
    cudaGetSymbolAddress((void**)&khi,  g_khi);
    cudaGetSymbolAddress((void**)&klo,  g_klo);
    cudaGetSymbolAddress((void**)&vp,   g_v);

    cudaFuncSetAttribute(gemm_f16x2<0>, cudaFuncAttributeMaxDynamicSharedMemorySize, DYN_SMEM);
    cudaFuncSetAttribute(gemm_f16x2<1>, cudaFuncAttributeMaxDynamicSharedMemorySize, DYN_SMEM);
    cudaFuncSetAttribute(gemm_f16x2<2>, cudaFuncAttributeMaxDynamicSharedMemorySize, DYN_SMEM);

    const int nsplit = (NDIM * NDIM) / (256 * 4);  // 16384 blocks per tensor
    dim3 ggrid(NDIM / 128, NDIM / 128);
    dim3 gblk(256);

    // Launch 0: all four hi/lo splits
    split_hi_lo4<<<dim3(nsplit, 1, 4), 256>>>(
        x, xhi, xlo, Wq, wqhi, wqlo, Wk, wkhi, wklo, Wv, wvhi, wvlo);

    // q = (x @ Wq^T + bq) / 64   (fold logit scale into q before split)
    gemm_f16x2<1><<<ggrid, gblk, DYN_SMEM>>>(xhi, xlo, wqhi, wqlo, bq, 1.0f / 64.0f, nullptr, qhi, qlo);
    // k = x @ Wk^T + bk
    gemm_f16x2<1><<<ggrid, gblk, DYN_SMEM>>>(xhi, xlo, wkhi, wklo, bk, 1.0f, nullptr, khi, klo);
    // v = x @ Wv^T + bv
    gemm_f16x2<0><<<ggrid, gblk, DYN_SMEM>>>(xhi, xlo, wvhi, wvlo, bv, 1.0f, vp, nullptr, nullptr);
    // S = q @ k^T  (scale already folded)
    gemm_f16x2<2><<<ggrid, gblk, DYN_SMEM>>>(qhi, qlo, khi, klo, nullptr, 1.0f, out, nullptr, nullptr);
    // out = softmax(S) * v (in place)
    softmax_mul<<<NDIM, 256>>>(out, vp, out);
}

// round 13
// speedup vs baseline: 1.0585x; 1.0585x over previous
#include <cuda_runtime.h>
#include <cuda_fp16.h>
#include <math.h>
#include <stdint.h>

#define NDIM 4096

// ===================== scratch (no allocation allowed) =====================
__device__ __half g_xhi[(size_t)NDIM * NDIM];
__device__ __half g_xlo[(size_t)NDIM * NDIM];
__device__ __half g_wqhi[(size_t)NDIM * NDIM];
__device__ __half g_wqlo[(size_t)NDIM * NDIM];
__device__ __half g_wkhi[(size_t)NDIM * NDIM];
__device__ __half g_wklo[(size_t)NDIM * NDIM];
__device__ __half g_wvhi[(size_t)NDIM * NDIM];
__device__ __half g_wvlo[(size_t)NDIM * NDIM];
__device__ __half g_qhi[(size_t)NDIM * NDIM];
__device__ __half g_qlo[(size_t)NDIM * NDIM];
__device__ __half g_khi[(size_t)NDIM * NDIM];
__device__ __half g_klo[(size_t)NDIM * NDIM];
__device__ float  g_v  [(size_t)NDIM * NDIM];

// ===================== small PTX helpers =====================
__device__ __forceinline__ uint32_t smem_u32(const void* p) {
    uint32_t a;
    asm("{ .reg .u64 t; cvta.to.shared.u64 t, %1; cvt.u32.u64 %0, t; }" : "=r"(a) : "l"(p));
    return a;
}
__device__ __forceinline__ void cp16(uint32_t s, const void* g) {
    asm volatile("cp.async.cg.shared.global [%0], [%1], 16;" :: "r"(s), "l"(g));
}
#define CP_COMMIT() asm volatile("cp.async.commit_group;" ::: "memory")
#define CP_WAIT(n)  asm volatile("cp.async.wait_group %0;" :: "n"(n) : "memory")

__device__ __forceinline__ void ldsm4(uint32_t* r, uint32_t addr) {
    asm volatile("ldmatrix.sync.aligned.m8n8.x4.shared.b16 {%0,%1,%2,%3}, [%4];"
        : "=r"(r[0]), "=r"(r[1]), "=r"(r[2]), "=r"(r[3]) : "r"(addr));
}
// fp16 inputs, fp32 accumulate (main term)
__device__ __forceinline__ void mma_f32(float* c, const uint32_t* a, uint32_t b0, uint32_t b1) {
    asm volatile("mma.sync.aligned.m16n8k16.row.col.f32.f16.f16.f32 "
        "{%0,%1,%2,%3},{%4,%5,%6,%7},{%8,%9},{%0,%1,%2,%3};"
        : "+f"(c[0]), "+f"(c[1]), "+f"(c[2]), "+f"(c[3])
        : "r"(a[0]), "r"(a[1]), "r"(a[2]), "r"(a[3]), "r"(b0), "r"(b1));
}
// fp16 inputs, fp16 accumulate (correction terms)
__device__ __forceinline__ void mma_f16(uint32_t* c, const uint32_t* a, uint32_t b0, uint32_t b1) {
    asm volatile("mma.sync.aligned.m16n8k16.row.col.f16.f16.f16.f16 "
        "{%0,%1},{%2,%3,%4,%5},{%6,%7},{%0,%1};"
        : "+r"(c[0]), "+r"(c[1])
        : "r"(a[0]), "r"(a[1]), "r"(a[2]), "r"(a[3]), "r"(b0), "r"(b1));
}

// Tile rows are 64B (4 x 16B chunks); chunk permuted by (row>>1)&3.
__device__ __forceinline__ uint32_t sw_off(int row, int c) {
    return row * 64 + ((c ^ ((row >> 1) & 3)) << 4);
}

// ===================== merged fp32 -> fp16 hi/lo split (z selects tensor) ==
__global__ void __launch_bounds__(256)
split_hi_lo4(const float* __restrict__ i0, __half* __restrict__ h0p, __half* __restrict__ l0p,
             const float* __restrict__ i1, __half* __restrict__ h1p, __half* __restrict__ l1p,
             const float* __restrict__ i2, __half* __restrict__ h2p, __half* __restrict__ l2p,
             const float* __restrict__ i3, __half* __restrict__ h3p, __half* __restrict__ l3p)
{
    const float* in;
    __half *hi, *lo;
    switch (blockIdx.z) {
        case 0: in = i0; hi = h0p; lo = l0p; break;
        case 1: in = i1; hi = h1p; lo = l1p; break;
        case 2: in = i2; hi = h2p; lo = l2p; break;
        default: in = i3; hi = h3p; lo = l3p; break;
    }
    size_t i = ((size_t)blockIdx.x * 256 + threadIdx.x) * 4;
    float4 v = *(const float4*)(in + i);
    __half a0 = __float2half_rn(v.x), a1 = __float2half_rn(v.y);
    __half a2 = __float2half_rn(v.z), a3 = __float2half_rn(v.w);
    __half b0 = __float2half_rn(v.x - __half2float(a0));
    __half b1 = __float2half_rn(v.y - __half2float(a1));
    __half b2 = __float2half_rn(v.z - __half2float(a2));
    __half b3 = __float2half_rn(v.w - __half2float(a3));
    *(__half2*)(hi + i)     = __halves2half2(a0, a1);
    *(__half2*)(hi + i + 2) = __halves2half2(a2, a3);
    *(__half2*)(lo + i)     = __halves2half2(b0, b1);
    *(__half2*)(lo + i + 2) = __halves2half2(b2, b3);
}

// ===================== HMMA GEMM =====================
// C = A*B^T, A ~ Ahi+Alo, B ~ Bhi+Blo (fp16 2-term split).
// hh -> fp32 acc; lh + hl -> shared fp16 acc.
// CTA tile 128(m)x64(n), BK=32, 4-stage cp.async, 8 warps @ 32x32, 2 CTAs/SM.
// MODE 0: Cf = alpha*(acc + bias[n])                  (v projection)
// MODE 1: split(alpha*(acc + bias[n])) -> Chi, Clo    (q/k projections)
// MODE 2: Cf = alpha*acc                              (attention logits)
#define NSTAGE 4
#define STAGE_B 24576
#define OFF_AHI 0
#define OFF_ALO 8192
#define OFF_BHI 16384
#define OFF_BLO 20480
#define DYN_SMEM (NSTAGE * STAGE_B)

__device__ __forceinline__ void load_stage(
    uint32_t sb, int stage, int k0, int m0, int n0, int tid,
    const __half* __restrict__ Ahi, const __half* __restrict__ Alo,
    const __half* __restrict__ Bhi, const __half* __restrict__ Blo)
{
    const uint32_t st = sb + stage * STAGE_B;
    // A: 128 rows x 64B, 512 chunks, 2 per thread (hi & lo each)
#pragma unroll
    for (int i = 0; i < 2; i++) {
        const int slot = tid + i * 256;
        const int r = slot >> 2;
        const int c = slot & 3;
        const uint32_t sw = sw_off(r, c);
        const size_t ga = (size_t)(m0 + r) * NDIM + k0 + c * 8;
        cp16(st + OFF_AHI + sw, Ahi + ga);
        cp16(st + OFF_ALO + sw, Alo + ga);
    }
    // B: 64 rows x 64B, 256 chunks, 1 per thread (hi & lo each)
    {
        const int r = tid >> 2;
        const int c = tid & 3;
        const uint32_t sw = sw_off(r, c);
        const size_t gb = (size_t)(n0 + r) * NDIM + k0 + c * 8;
        cp16(st + OFF_BHI + sw, Bhi + gb);
        cp16(st + OFF_BLO + sw, Blo + gb);
    }
}

template<int MODE>
__global__ void __launch_bounds__(256, 2)
gemm_f16x2(const __half* __restrict__ Ahi, const __half* __restrict__ Alo,
           const __half* __restrict__ Bhi, const __half* __restrict__ Blo,
           const float* __restrict__ bias, float alpha,
           float* __restrict__ Cf,
           __half* __restrict__ Chi, __half* __restrict__ Clo)
{
    extern __shared__ char dynsmem[];
    const uint32_t sb = smem_u32(dynsmem);
    const int tid  = threadIdx.x;
    const int lane = tid & 31;
    const int w    = tid >> 5;           // 0..7
    const int wm0  = (w & 3) * 32;       // 4 warps along m
    const int wn0  = (w >> 2) * 32;      // 2 warps along n
    const int m0 = blockIdx.y * 128;
    const int n0 = blockIdx.x * 64;

    float acc[2][4][4];
    uint32_t acc16[2][4][2];
#pragma unroll
    for (int mt = 0; mt < 2; mt++)
#pragma unroll
        for (int nt = 0; nt < 4; nt++) {
#pragma unroll
            for (int e = 0; e < 4; e++) acc[mt][nt][e] = 0.0f;
            acc16[mt][nt][0] = 0u; acc16[mt][nt][1] = 0u;
        }

    // Precompute per-thread ldsm offsets (stage-base added per iter).
    const int arow  = (lane & 15);
    const int ahalf = (lane >> 4);
    uint32_t aoff[2][2], boff[2][2];     // [ks][mt] / [ks][p]
#pragma unroll
    for (int ks = 0; ks < 2; ks++) {
        const int c = ks * 2 + ahalf;
#pragma unroll
        for (int mt = 0; mt < 2; mt++)
            aoff[ks][mt] = OFF_AHI + sw_off(wm0 + mt * 16 + arow, c);
#pragma unroll
        for (int p = 0; p < 2; p++)
            boff[ks][p] = OFF_BHI + sw_off(wn0 + p * 16 + arow, c);
    }

#pragma unroll
    for (int s = 0; s < NSTAGE - 1; s++) {
        load_stage(sb, s, s * 32, m0, n0, tid, Ahi, Alo, Bhi, Blo);
        CP_COMMIT();
    }

    for (int i = 0; i < NDIM / 32; i++) {
        CP_WAIT(NSTAGE - 2);
        __syncthreads();
        const int j = i + NSTAGE - 1;
        if (j < NDIM / 32)
            load_stage(sb, j & (NSTAGE - 1), j * 32, m0, n0, tid, Ahi, Alo, Bhi, Blo);
        CP_COMMIT();

        const uint32_t st = sb + (i & (NSTAGE - 1)) * STAGE_B;
#pragma unroll
        for (int ks = 0; ks < 2; ks++) {
            uint32_t bh[2][4], bl[2][4];
#pragma unroll
            for (int p = 0; p < 2; p++) {
                ldsm4(bh[p], st + boff[ks][p]);
                ldsm4(bl[p], st + boff[ks][p] + (OFF_BLO - OFF_BHI));
            }
#pragma unroll
            for (int mt = 0; mt < 2; mt++) {
                uint32_t ah[4], al[4];
                ldsm4(ah, st + aoff[ks][mt]);
                ldsm4(al, st + aoff[ks][mt] + (OFF_ALO - OFF_AHI));
                // main hh (fp32 acc, 4 independent)
                mma_f32(acc[mt][0], ah, bh[0][0], bh[0][2]);
                mma_f32(acc[mt][1], ah, bh[0][1], bh[0][3]);
                mma_f32(acc[mt][2], ah, bh[1][0], bh[1][2]);
                mma_f32(acc[mt][3], ah, bh[1][1], bh[1][3]);
                // corrections lh then hl (fp16 acc)
                mma_f16(acc16[mt][0], al, bh[0][0], bh[0][2]);
                mma_f16(acc16[mt][1], al, bh[0][1], bh[0][3]);
                mma_f16(acc16[mt][2], al, bh[1][0], bh[1][2]);
                mma_f16(acc16[mt][3], al, bh[1][1], bh[1][3]);
                mma_f16(acc16[mt][0], ah, bl[0][0], bl[0][2]);
                mma_f16(acc16[mt][1], ah, bl[0][1], bl[0][3]);
                mma_f16(acc16[mt][2], ah, bl[1][0], bl[1][2]);
                mma_f16(acc16[mt][3], ah, bl[1][1], bl[1][3]);
            }
        }
    }

    // ---------------- epilogue ----------------
#pragma unroll
    for (int mt = 0; mt < 2; mt++) {
#pragma unroll
        for (int nt = 0; nt < 4; nt++) {
            const int r0  = m0 + wm0 + mt * 16 + (lane >> 2);
            const int col = n0 + wn0 + nt * 8 + (lane & 3) * 2;
            const float* cc = acc[mt][nt];
#pragma unroll
            for (int h = 0; h < 2; h++) {       // rows r0, r0+8
                const int r = r0 + h * 8;
                __half2 cr = *(__half2*)&acc16[mt][nt][h];
                float f0 = cc[2 * h + 0] + __half2float(__low2half(cr));
                float f1 = cc[2 * h + 1] + __half2float(__high2half(cr));
                if (MODE == 2) {
                    *(float2*)&Cf[(size_t)r * NDIM + col] = make_float2(f0 * alpha, f1 * alpha);
                } else if (MODE == 0) {
                    f0 = alpha * (f0 + __ldg(&bias[col]));
                    f1 = alpha * (f1 + __ldg(&bias[col + 1]));
                    *(float2*)&Cf[(size_t)r * NDIM + col] = make_float2(f0, f1);
                } else {
                    f0 = alpha * (f0 + __ldg(&bias[col]));
                    f1 = alpha * (f1 + __ldg(&bias[col + 1]));
                    __half h0 = __float2half_rn(f0), h1 = __float2half_rn(f1);
                    __half l0 = __float2half_rn(f0 - __half2float(h0));
                    __half l1 = __float2half_rn(f1 - __half2float(h1));
                    *(__half2*)&Chi[(size_t)r * NDIM + col] = __halves2half2(h0, h1);
                    *(__half2*)&Clo[(size_t)r * NDIM + col] = __halves2half2(l0, l1);
                }
            }
        }
    }
}

// ===================== softmax(S) * v, in place on d_out =====================
__global__ void __launch_bounds__(256)
softmax_mul(const float* __restrict__ S, const float* __restrict__ V, float* __restrict__ out)
{
    __shared__ float red[256];
    const int row = blockIdx.x;
    const int tid = threadIdx.x;
    const float* s = S + (size_t)row * NDIM;

    float vals[16];
    float m = -INFINITY;
#pragma unroll
    for (int i = 0; i < 16; i++) {
        vals[i] = s[tid + i * 256];
        m = fmaxf(m, vals[i]);
    }
    red[tid] = m;
    __syncthreads();
#pragma unroll
    for (int w = 128; w > 0; w >>= 1) {
        if (tid < w) red[tid] = fmaxf(red[tid], red[tid + w]);
        __syncthreads();
    }
    m = red[0];
    __syncthreads();

    float sum = 0.0f;
#pragma unroll
    for (int i = 0; i < 16; i++) {
        vals[i] = expf(vals[i] - m);
        sum += vals[i];
    }
    red[tid] = sum;
    __syncthreads();
#pragma unroll
    for (int w = 128; w > 0; w >>= 1) {
        if (tid < w) red[tid] += red[tid + w];
        __syncthreads();
    }
    const float inv = 1.0f / red[0];

    const float* v = V + (size_t)row * NDIM;
    float* o = out + (size_t)row * NDIM;
#pragma unroll
    for (int i = 0; i < 16; i++) {
        const int c = tid + i * 256;
        o[c] = vals[i] * inv * v[c];
    }
}

// ===================== launch =====================
extern "C" void kernel_launch(void* const* d_in, const int* in_sizes, int n_in,
                              void* d_out, int out_size)
{
    const float* x  = (const float*)d_in[0];
    const float* Wq = (const float*)d_in[1];
    const float* bq = (const float*)d_in[2];
    const float* Wk = (const float*)d_in[3];
    const float* bk = (const float*)d_in[4];
    const float* Wv = (const float*)d_in[5];
    const float* bv = (const float*)d_in[6];
    float* out = (float*)d_out;

    __half *xhi, *xlo, *wqhi, *wqlo, *wkhi, *wklo, *wvhi, *wvlo;
    __half *qhi, *qlo, *khi, *klo;
    float* vp;
    cudaGetSymbolAddress((void**)&xhi,  g_xhi);
    cudaGetSymbolAddress((void**)&xlo,  g_xlo);
    cudaGetSymbolAddress((void**)&wqhi, g_wqhi);
    cudaGetSymbolAddress((void**)&wqlo, g_wqlo);
    cudaGetSymbolAddress((void**)&wkhi, g_wkhi);
    cudaGetSymbolAddress((void**)&wklo, g_wklo);
    cudaGetSymbolAddress((void**)&wvhi, g_wvhi);
    cudaGetSymbolAddress((void**)&wvlo, g_wvlo);
    cudaGetSymbolAddress((void**)&qhi,  g_qhi);
    cudaGetSymbolAddress((void**)&qlo,  g_qlo);
    cudaGetSymbolAddress((void**)&khi,  g_khi);
    cudaGetSymbolAddress((void**)&klo,  g_klo);
    cudaGetSymbolAddress((void**)&vp,   g_v);

    cudaFuncSetAttribute(gemm_f16x2<0>, cudaFuncAttributeMaxDynamicSharedMemorySize, DYN_SMEM);
    cudaFuncSetAttribute(gemm_f16x2<1>, cudaFuncAttributeMaxDynamicSharedMemorySize, DYN_SMEM);
    cudaFuncSetAttribute(gemm_f16x2<2>, cudaFuncAttributeMaxDynamicSharedMemorySize, DYN_SMEM);

    const int nsplit = (NDIM * NDIM) / (256 * 4);  // 16384 blocks per tensor
    dim3 ggrid(NDIM / 64, NDIM / 128);             // (64, 32)
    dim3 gblk(256);

    // Launch 0: all four hi/lo splits
    split_hi_lo4<<<dim3(nsplit, 1, 4), 256>>>(
        x, xhi, xlo, Wq, wqhi, wqlo, Wk, wkhi, wklo, Wv, wvhi, wvlo);

    // q = (x @ Wq^T + bq) / 64   (fold logit scale into q)
    gemm_f16x2<1><<<ggrid, gblk, DYN_SMEM>>>(xhi, xlo, wqhi, wqlo, bq, 1.0f / 64.0f, nullptr, qhi, qlo);
    // k = x @ Wk^T + bk
    gemm_f16x2<1><<<ggrid, gblk, DYN_SMEM>>>(xhi, xlo, wkhi, wklo, bk, 1.0f, nullptr, khi, klo);
    // v = x @ Wv^T + bv
    gemm_f16x2<0><<<ggrid, gblk, DYN_SMEM>>>(xhi, xlo, wvhi, wvlo, bv, 1.0f, vp, nullptr, nullptr);
    // S = q @ k^T  (scale folded)
    gemm_f16x2<2><<<ggrid, gblk, DYN_SMEM>>>(qhi, qlo, khi, klo, nullptr, 1.0f, out, nullptr, nullptr);
    // out = softmax(S) * v (in place)
    softmax_mul<<<NDIM, 256>>>(out, vp, out);
}